// round 3
// baseline (speedup 1.0000x reference)
#include <cuda_runtime.h>

#define B   8
#define L   4096
#define D   1024
#define DQK 1024
#define M   (B * L)           // 32768 tokens
#define BLD (B * L * D)       // 33554432

// ---------------- scratch (device globals; no allocation allowed) ----------
__device__ float g_q[(size_t)M * DQK];     // 128 MiB
__device__ float g_k[(size_t)M * DQK];     // 128 MiB
__device__ float g_res[(size_t)M * D];     // 128 MiB
__device__ float g_scan[(size_t)M * D];    // 128 MiB
__device__ float g_probs[M];
__device__ int   g_chunkid[M];
__device__ int   g_blidx[M];
__device__ int   g_nch[B];
__device__ float g_auxb[B];

// ---------------- Kernel 1: fp32 SGEMM  C[M,3072] = tokens @ [W_qk | W_res] -
// Classic 128x128x8 tiling, 256 threads, 8x8 per-thread microtile.
__global__ __launch_bounds__(256) void sgemm_kernel(
    const float* __restrict__ A,      // tokens [M, 1024]
    const float* __restrict__ Wqk,    // [1024, 2048]
    const float* __restrict__ Wres)   // [1024, 1024]
{
    const int K = 1024;
    int m0 = blockIdx.x * 128;
    int n0 = blockIdx.y * 128;

    const float* Bp; int ldb; float* Cp;
    if (n0 < 2048) { Bp = Wqk + n0;          ldb = 2048; }
    else           { Bp = Wres + (n0 - 2048); ldb = 1024; }
    if (n0 < 1024)      Cp = g_q   + n0;
    else if (n0 < 2048) Cp = g_k   + (n0 - 1024);
    else                Cp = g_res + (n0 - 2048);

    __shared__ float As[8][128];
    __shared__ float Bs[8][128];

    int tid = threadIdx.x;
    int tx = tid & 15, ty = tid >> 4;

    int arow = tid >> 1;            // 0..127
    int acol = (tid & 1) * 4;       // 0 or 4
    int brow = tid >> 5;            // 0..7
    int bcol = (tid & 31) * 4;      // 0..124

    const float* Aptr = A  + (size_t)(m0 + arow) * K + acol;
    const float* Bptr = Bp + (size_t)brow * ldb + bcol;

    float acc[8][8];
#pragma unroll
    for (int i = 0; i < 8; i++)
#pragma unroll
        for (int j = 0; j < 8; j++) acc[i][j] = 0.f;

    for (int k0 = 0; k0 < K; k0 += 8) {
        float4 av = *(const float4*)(Aptr + k0);
        float4 bv = *(const float4*)(Bptr + (size_t)k0 * ldb);
        As[acol + 0][arow] = av.x;
        As[acol + 1][arow] = av.y;
        As[acol + 2][arow] = av.z;
        As[acol + 3][arow] = av.w;
        *(float4*)&Bs[brow][bcol] = bv;
        __syncthreads();
#pragma unroll
        for (int kk = 0; kk < 8; kk++) {
            float a[8], bb[8];
            *(float4*)(a)      = *(const float4*)&As[kk][ty * 4];
            *(float4*)(a + 4)  = *(const float4*)&As[kk][64 + ty * 4];
            *(float4*)(bb)     = *(const float4*)&Bs[kk][tx * 4];
            *(float4*)(bb + 4) = *(const float4*)&Bs[kk][64 + tx * 4];
#pragma unroll
            for (int i = 0; i < 8; i++)
#pragma unroll
                for (int j = 0; j < 8; j++)
                    acc[i][j] = fmaf(a[i], bb[j], acc[i][j]);
        }
        __syncthreads();
    }

#pragma unroll
    for (int i = 0; i < 8; i++) {
        int r = (i < 4) ? (ty * 4 + i) : (64 + ty * 4 + i - 4);
        float* crow = Cp + (size_t)(m0 + r) * 1024;
        *(float4*)(crow + tx * 4)      = make_float4(acc[i][0], acc[i][1], acc[i][2], acc[i][3]);
        *(float4*)(crow + 64 + tx * 4) = make_float4(acc[i][4], acc[i][5], acc[i][6], acc[i][7]);
    }
}

// ---------------- Kernel 2: per-token cosine -> probs -----------------------
__global__ __launch_bounds__(128) void probs_kernel(const float* __restrict__ start_key)
{
    int token = blockIdx.x;
    int l = token & (L - 1);
    const float4* qv = (const float4*)(g_q + (size_t)token * DQK);
    const float4* kv = (l == 0) ? (const float4*)start_key
                                : (const float4*)(g_k + (size_t)(token - 1) * DQK);
    float dot = 0.f, qq = 0.f, kk = 0.f;
    for (int i = threadIdx.x; i < DQK / 4; i += 128) {
        float4 a = qv[i], c = kv[i];
        dot += a.x * c.x + a.y * c.y + a.z * c.z + a.w * c.w;
        qq  += a.x * a.x + a.y * a.y + a.z * a.z + a.w * a.w;
        kk  += c.x * c.x + c.y * c.y + c.z * c.z + c.w * c.w;
    }
#pragma unroll
    for (int o = 16; o; o >>= 1) {
        dot += __shfl_down_sync(0xffffffffu, dot, o);
        qq  += __shfl_down_sync(0xffffffffu, qq,  o);
        kk  += __shfl_down_sync(0xffffffffu, kk,  o);
    }
    __shared__ float sd[4], sq[4], sk[4];
    int w = threadIdx.x >> 5;
    if ((threadIdx.x & 31) == 0) { sd[w] = dot; sq[w] = qq; sk[w] = kk; }
    __syncthreads();
    if (threadIdx.x == 0) {
        dot = sd[0] + sd[1] + sd[2] + sd[3];
        qq  = sq[0] + sq[1] + sq[2] + sq[3];
        kk  = sk[0] + sk[1] + sk[2] + sk[3];
        float denom = fmaxf(sqrtf(qq) * sqrtf(kk), 1e-8f);
        g_probs[token] = (1.0f - dot / denom) * 0.5f;
    }
}

// ---------------- Kernel 3: per-batch boundary scan + aux -------------------
__global__ __launch_bounds__(1024) void boundary_kernel()
{
    int b = blockIdx.x;
    int tid = threadIdx.x;
    __shared__ int   s[1024];
    __shared__ float sf[1024];

    int l0 = tid * 4;
    float p[4]; int bd[4]; int cnt = 0; float psum = 0.f;
#pragma unroll
    for (int i = 0; i < 4; i++) {
        int l = l0 + i;
        p[i] = g_probs[b * L + l];
        bd[i] = (l == 0) || (p[i] > 0.5f);
        cnt += bd[i];
        psum += p[i];
    }
    s[tid] = cnt;
    sf[tid] = psum;
    __syncthreads();
    // inclusive Hillis-Steele scan over thread counts
    for (int off = 1; off < 1024; off <<= 1) {
        int v = (tid >= off) ? s[tid - off] : 0;
        __syncthreads();
        if (tid >= off) s[tid] += v;
        __syncthreads();
    }
    int incl = s[tid];
    int base = incl - cnt;
    int total = s[1023];
    int run = base;
#pragma unroll
    for (int i = 0; i < 4; i++) {
        int l = l0 + i;
        if (bd[i]) { g_blidx[b * L + run] = l; run++; }
        g_chunkid[b * L + l] = run - 1;
    }
    __syncthreads();
    for (int off = 512; off > 0; off >>= 1) {
        if (tid < off) sf[tid] += sf[tid + off];
        __syncthreads();
    }
    if (tid == 0) {
        float F = (float)total / (float)L;
        float G = sf[0] / (float)L;
        // (N/(N-1)) * ((N-1)FG + (1-F)(1-G)), N=6
        g_auxb[b] = 1.2f * (5.0f * F * G + (1.0f - F) * (1.0f - G));
        g_nch[b] = total;
    }
}

// ---------------- Kernel 4a: zero padded chunk slots of downsampled ---------
__global__ __launch_bounds__(256) void zero_down_kernel(float* __restrict__ out)
{
    int row = blockIdx.x;          // b*L + j
    int b = row >> 12;
    int j = row & (L - 1);
    if (j < g_nch[b]) return;
    float4* o = (float4*)(out + (size_t)row * D);
    o[threadIdx.x] = make_float4(0.f, 0.f, 0.f, 0.f);
}

// ---------------- Kernel 4b: chunk-axis EMA scan + downsampled write --------
__global__ __launch_bounds__(128) void chunk_scan_kernel(
    const float* __restrict__ tokens, float* __restrict__ out)
{
    int b = blockIdx.y;
    int d = blockIdx.x * 128 + threadIdx.x;
    int nch = g_nch[b];
    const int*   bl = g_blidx + b * L;
    const float* pr = g_probs + b * L;
    float h = 0.f;
    for (int j = 0; j < nch; j++) {
        int   l = bl[j];
        float p = pr[l];
        float t = tokens[(size_t)(b * L + l) * D + d];
        float x = p * t;
        out[(size_t)(b * L + j) * D + d] = x;          // downsampled
        h = fmaf(1.0f - p, h, x);                      // h = (1-p)h + p t
        g_scan[(size_t)(b * L + j) * D + d] = h;
    }
}

// ---------------- Kernel 5: ups = gather(scan) + res + b_res ----------------
__global__ __launch_bounds__(256) void ups_kernel(
    float* __restrict__ out, const float* __restrict__ b_res)
{
    int row = blockIdx.x;          // b*L + l
    int b = row >> 12;
    int cid = g_chunkid[row];
    const float4* sc = (const float4*)(g_scan + (size_t)(b * L + cid) * D);
    const float4* rs = (const float4*)(g_res + (size_t)row * D);
    const float4* br = (const float4*)b_res;
    float4* o = (float4*)(out + (size_t)BLD + (size_t)row * D);
    int t = threadIdx.x;
    float4 a = sc[t], c = rs[t], e = br[t];
    o[t] = make_float4(a.x + c.x + e.x, a.y + c.y + e.y,
                       a.z + c.z + e.z, a.w + c.w + e.w);
}

// ---------------- Kernel 6: finalize aux scalar -----------------------------
__global__ void aux_final_kernel(float* __restrict__ out)
{
    float s = 0.f;
    for (int i = 0; i < B; i++) s += g_auxb[i];
    out[(size_t)2 * BLD] = (s / (float)B) * 0.03f;
}

// ---------------- launch ----------------------------------------------------
extern "C" void kernel_launch(void* const* d_in, const int* in_sizes, int n_in,
                              void* d_out, int out_size)
{
    const float* tokens = (const float*)d_in[0];
    const float* Wqk    = (const float*)d_in[1];
    const float* skey   = (const float*)d_in[2];
    const float* Wres   = (const float*)d_in[3];
    const float* bres   = (const float*)d_in[4];
    float* out = (float*)d_out;

    sgemm_kernel<<<dim3(M / 128, 3072 / 128), 256>>>(tokens, Wqk, Wres);
    probs_kernel<<<M, 128>>>(skey);
    boundary_kernel<<<B, 1024>>>();
    zero_down_kernel<<<M, 256>>>(out);
    chunk_scan_kernel<<<dim3(D / 128, B), 128>>>(tokens, out);
    ups_kernel<<<M, 256>>>(out, bres);
    aux_final_kernel<<<1, 1>>>(out);
}

// round 5
// speedup vs baseline: 2.3581x; 2.3581x over previous
#include <cuda_runtime.h>
#include <cuda_bf16.h>
#include <cstdint>

#define B   8
#define L   4096
#define D   1024
#define DQK 1024
#define M   (B * L)           // 32768 tokens
#define BLD ((size_t)M * D)   // 33554432
#define NTOT 3072

// ---------------- scratch (device globals; no allocation allowed) ----------
__device__ float g_q[(size_t)M * DQK];     // 128 MiB
__device__ float g_k[(size_t)M * DQK];     // 128 MiB
__device__ float g_res[(size_t)M * D];     // 128 MiB
__device__ float g_scan[(size_t)M * D];    // 128 MiB
__device__ float g_probs[M];
__device__ int   g_chunkid[M];
__device__ int   g_blidx[M];
__device__ int   g_nch[B];
__device__ float g_auxb[B];

// bf16 3-way splits of A (tokens) and B (combined weights, TRANSPOSED: [n][k])
__device__ __nv_bfloat16 g_Ahi [(size_t)M * 1024];
__device__ __nv_bfloat16 g_Amid[(size_t)M * 1024];
__device__ __nv_bfloat16 g_Alo [(size_t)M * 1024];
__device__ __nv_bfloat16 g_Bhi [(size_t)NTOT * 1024];
__device__ __nv_bfloat16 g_Bmid[(size_t)NTOT * 1024];
__device__ __nv_bfloat16 g_Blo [(size_t)NTOT * 1024];

// ======================= helpers ===========================================
__device__ __forceinline__ uint32_t smem_u32(const void* p) {
    uint32_t a;
    asm("{ .reg .u64 t; cvta.to.shared.u64 t, %1; cvt.u32.u64 %0, t; }"
        : "=r"(a) : "l"(p));
    return a;
}
__device__ __forceinline__ void cp_async16(uint32_t saddr, const void* gaddr) {
    asm volatile("cp.async.cg.shared.global [%0], [%1], 16;"
                 :: "r"(saddr), "l"(gaddr));
}
__device__ __forceinline__ void cp_commit() {
    asm volatile("cp.async.commit_group;");
}
__device__ __forceinline__ void cp_wait1() {
    asm volatile("cp.async.wait_group 1;");
}
__device__ __forceinline__ void cp_wait0() {
    asm volatile("cp.async.wait_group 0;");
}
__device__ __forceinline__ void ldsm_x4(uint32_t addr, uint32_t& r0, uint32_t& r1,
                                        uint32_t& r2, uint32_t& r3) {
    asm volatile("ldmatrix.sync.aligned.m8n8.x4.shared.b16 {%0,%1,%2,%3}, [%4];"
                 : "=r"(r0), "=r"(r1), "=r"(r2), "=r"(r3) : "r"(addr));
}
__device__ __forceinline__ void mma_bf16(float& c0, float& c1, float& c2, float& c3,
                                         uint32_t a0, uint32_t a1, uint32_t a2, uint32_t a3,
                                         uint32_t b0, uint32_t b1) {
    asm volatile(
        "mma.sync.aligned.m16n8k16.row.col.f32.bf16.bf16.f32 "
        "{%0,%1,%2,%3}, {%4,%5,%6,%7}, {%8,%9}, {%0,%1,%2,%3};"
        : "+f"(c0), "+f"(c1), "+f"(c2), "+f"(c3)
        : "r"(a0), "r"(a1), "r"(a2), "r"(a3), "r"(b0), "r"(b1));
}

// ---------------- Prep 1: split tokens -> bf16 hi/mid/lo --------------------
__global__ __launch_bounds__(256) void split_a_kernel(const float* __restrict__ A)
{
    size_t i4 = (size_t)blockIdx.x * 256 + threadIdx.x;   // float4 index
    float4 v = ((const float4*)A)[i4];
    float x[4] = {v.x, v.y, v.z, v.w};
    unsigned short h[4], mm[4], ll[4];
#pragma unroll
    for (int j = 0; j < 4; j++) {
        __nv_bfloat16 bh = __float2bfloat16_rn(x[j]);
        float r1 = x[j] - __bfloat162float(bh);
        __nv_bfloat16 bm = __float2bfloat16_rn(r1);
        float r2 = r1 - __bfloat162float(bm);
        __nv_bfloat16 bl = __float2bfloat16_rn(r2);
        h[j]  = __bfloat16_as_ushort(bh);
        mm[j] = __bfloat16_as_ushort(bm);
        ll[j] = __bfloat16_as_ushort(bl);
    }
    ((uint2*)g_Ahi)[i4]  = make_uint2((unsigned)h[0]  | ((unsigned)h[1]  << 16),
                                      (unsigned)h[2]  | ((unsigned)h[3]  << 16));
    ((uint2*)g_Amid)[i4] = make_uint2((unsigned)mm[0] | ((unsigned)mm[1] << 16),
                                      (unsigned)mm[2] | ((unsigned)mm[3] << 16));
    ((uint2*)g_Alo)[i4]  = make_uint2((unsigned)ll[0] | ((unsigned)ll[1] << 16),
                                      (unsigned)ll[2] | ((unsigned)ll[3] << 16));
}

// ---------------- Prep 2: split + transpose weights -> [n][k] bf16 ----------
__global__ __launch_bounds__(256) void split_b_kernel(
    const float* __restrict__ Wqk, const float* __restrict__ Wres)
{
    int id = blockIdx.x * 256 + threadIdx.x;   // 0..393215
    int n  = id % NTOT;
    int kg = id / NTOT;                         // 0..127
    int k0 = kg * 8;
    unsigned short h[8], mm[8], ll[8];
#pragma unroll
    for (int j = 0; j < 8; j++) {
        int k = k0 + j;
        float x = (n < 2048) ? Wqk[(size_t)k * 2048 + n]
                             : Wres[(size_t)k * 1024 + (n - 2048)];
        __nv_bfloat16 bh = __float2bfloat16_rn(x);
        float r1 = x - __bfloat162float(bh);
        __nv_bfloat16 bm = __float2bfloat16_rn(r1);
        float r2 = r1 - __bfloat162float(bm);
        __nv_bfloat16 bl = __float2bfloat16_rn(r2);
        h[j]  = __bfloat16_as_ushort(bh);
        mm[j] = __bfloat16_as_ushort(bm);
        ll[j] = __bfloat16_as_ushort(bl);
    }
    size_t off = (size_t)n * 1024 + k0;  // bf16 elements
#define PACK4(a) make_uint4((unsigned)a[0] | ((unsigned)a[1] << 16), \
                            (unsigned)a[2] | ((unsigned)a[3] << 16), \
                            (unsigned)a[4] | ((unsigned)a[5] << 16), \
                            (unsigned)a[6] | ((unsigned)a[7] << 16))
    *(uint4*)((char*)g_Bhi  + off * 2) = PACK4(h);
    *(uint4*)((char*)g_Bmid + off * 2) = PACK4(mm);
    *(uint4*)((char*)g_Blo  + off * 2) = PACK4(ll);
#undef PACK4
}

// ---------------- Kernel 1: mma.sync split-bf16 GEMM ------------------------
// C[M, 3072] = tokens @ [W_qk | W_res].
// QK cols (0..2047): 6 bf16 products -> fp32-level accuracy (dot err ~1e-7).
// Res cols (2048..3071): 3 products (err ~1.5e-5, fine vs 1e-3 tolerance).
// CTA tile 128x128, warps 4(m) x 2(n), warp tile 32x64, K-chunks of 64.
#define TILE_B      16384           // one 128x64 bf16 tile (128B rows)
#define STAGE_BYTES (6 * TILE_B)    // 96 KB
#define GEMM_SMEM   (2 * STAGE_BYTES)

__device__ __forceinline__ void fill_stage(
    uint32_t st32, const char* const* gsrc, int chunk, int isres, int tid)
{
    int ntile = isres ? 4 : 6;
    for (int t = 0; t < ntile; t++) {
        int arr = isres ? ((t < 2) ? t : t + 1) : t;   // res: {0,1,3,4}
#pragma unroll
        for (int it = 0; it < 4; it++) {
            int w = tid + it * 256;                    // 0..1023
            int row = w >> 3;
            int colB = (w & 7) * 16;
            const char* g = gsrc[arr] + (size_t)row * 2048 + chunk * 128 + colB;
            uint32_t dst = st32 + arr * TILE_B + row * 128
                         + (colB ^ ((row & 7) << 4));
            cp_async16(dst, g);
        }
    }
}

__global__ void __launch_bounds__(256, 1) gemm_kernel()
{
    extern __shared__ char smem[];
    uint32_t sb = smem_u32(smem);
    const int tid = threadIdx.x;
    const int lane = tid & 31;
    const int wid = tid >> 5;
    const int warp_m = wid & 3;          // 0..3 -> m offset 32*warp_m
    const int warp_n = wid >> 2;         // 0..1 -> n offset 64*warp_n
    const int m0 = blockIdx.y * 128;
    const int n0 = blockIdx.x * 128;
    const int isres = (n0 >= 2048);

    const char* gsrc[6];
    gsrc[0] = (const char*)g_Ahi  + (size_t)m0 * 2048;
    gsrc[1] = (const char*)g_Amid + (size_t)m0 * 2048;
    gsrc[2] = (const char*)g_Alo  + (size_t)m0 * 2048;
    gsrc[3] = (const char*)g_Bhi  + (size_t)n0 * 2048;
    gsrc[4] = (const char*)g_Bmid + (size_t)n0 * 2048;
    gsrc[5] = (const char*)g_Blo  + (size_t)n0 * 2048;

    float acc[2][8][4];
#pragma unroll
    for (int i = 0; i < 2; i++)
#pragma unroll
        for (int j = 0; j < 8; j++)
#pragma unroll
            for (int q = 0; q < 4; q++) acc[i][j][q] = 0.f;

    // per-thread ldmatrix address invariants
    const int aRow  = warp_m * 32 + (lane & 15);       // +16*mi later
    const int aXor  = (aRow & 7) << 4;
    const int aColB = (lane >> 4) * 16;                // 0/16
    const int bRow  = warp_n * 64 + (lane & 7) + ((lane >> 4) & 1) * 8; // +16*ng
    const int bXor  = (bRow & 7) << 4;
    const int bColB = ((lane >> 3) & 1) * 16;          // 0/16

    const signed char prodA[6] = {0, 1, 0, 1, 0, 2};
    const signed char prodB[6] = {3, 3, 4, 4, 5, 3};
    const int nprod = isres ? 3 : 6;

    fill_stage(sb, gsrc, 0, isres, tid);
    cp_commit();

    for (int c = 0; c < 16; c++) {
        uint32_t stage = sb + (c & 1) * STAGE_BYTES;
        if (c < 15) {
            fill_stage(sb + ((c + 1) & 1) * STAGE_BYTES, gsrc, c + 1, isres, tid);
            cp_commit();
            cp_wait1();
        } else {
            cp_wait0();
        }
        __syncthreads();

        for (int pp = 0; pp < nprod; pp++) {
            uint32_t aBase = stage + prodA[pp] * TILE_B;
            uint32_t bBase = stage + prodB[pp] * TILE_B;
#pragma unroll
            for (int ks = 0; ks < 4; ks++) {
                uint32_t a[2][4];
#pragma unroll
                for (int mi = 0; mi < 2; mi++) {
                    uint32_t addr = aBase + (aRow + mi * 16) * 128
                                  + ((ks * 32 + aColB) ^ aXor);
                    ldsm_x4(addr, a[mi][0], a[mi][1], a[mi][2], a[mi][3]);
                }
                uint32_t bb[4][4];
#pragma unroll
                for (int ng = 0; ng < 4; ng++) {
                    uint32_t addr = bBase + (bRow + ng * 16) * 128
                                  + ((ks * 32 + bColB) ^ bXor);
                    ldsm_x4(addr, bb[ng][0], bb[ng][1], bb[ng][2], bb[ng][3]);
                }
#pragma unroll
                for (int mi = 0; mi < 2; mi++)
#pragma unroll
                    for (int ng = 0; ng < 4; ng++) {
                        mma_bf16(acc[mi][ng*2][0],   acc[mi][ng*2][1],
                                 acc[mi][ng*2][2],   acc[mi][ng*2][3],
                                 a[mi][0], a[mi][1], a[mi][2], a[mi][3],
                                 bb[ng][0], bb[ng][1]);
                        mma_bf16(acc[mi][ng*2+1][0], acc[mi][ng*2+1][1],
                                 acc[mi][ng*2+1][2], acc[mi][ng*2+1][3],
                                 a[mi][0], a[mi][1], a[mi][2], a[mi][3],
                                 bb[ng][2], bb[ng][3]);
                    }
            }
        }
        __syncthreads();
    }

    // epilogue: write accumulators to the right destination region
    float* cbase; int coloff;
    if (n0 < 1024)      { cbase = g_q;   coloff = n0; }
    else if (n0 < 2048) { cbase = g_k;   coloff = n0 - 1024; }
    else                { cbase = g_res; coloff = n0 - 2048; }

#pragma unroll
    for (int mi = 0; mi < 2; mi++) {
        int r0 = m0 + warp_m * 32 + mi * 16 + (lane >> 2);
#pragma unroll
        for (int ni = 0; ni < 8; ni++) {
            int col = coloff + warp_n * 64 + ni * 8 + (lane & 3) * 2;
            *(float2*)&cbase[(size_t)r0 * 1024 + col] =
                make_float2(acc[mi][ni][0], acc[mi][ni][1]);
            *(float2*)&cbase[(size_t)(r0 + 8) * 1024 + col] =
                make_float2(acc[mi][ni][2], acc[mi][ni][3]);
        }
    }
}

// ---------------- Kernel 2: per-token cosine -> probs -----------------------
__global__ __launch_bounds__(128) void probs_kernel(const float* __restrict__ start_key)
{
    int token = blockIdx.x;
    int l = token & (L - 1);
    const float4* qv = (const float4*)(g_q + (size_t)token * DQK);
    const float4* kv = (l == 0) ? (const float4*)start_key
                                : (const float4*)(g_k + (size_t)(token - 1) * DQK);
    float dot = 0.f, qq = 0.f, kk = 0.f;
    for (int i = threadIdx.x; i < DQK / 4; i += 128) {
        float4 a = qv[i], c = kv[i];
        dot += a.x * c.x + a.y * c.y + a.z * c.z + a.w * c.w;
        qq  += a.x * a.x + a.y * a.y + a.z * a.z + a.w * a.w;
        kk  += c.x * c.x + c.y * c.y + c.z * c.z + c.w * c.w;
    }
#pragma unroll
    for (int o = 16; o; o >>= 1) {
        dot += __shfl_down_sync(0xffffffffu, dot, o);
        qq  += __shfl_down_sync(0xffffffffu, qq,  o);
        kk  += __shfl_down_sync(0xffffffffu, kk,  o);
    }
    __shared__ float sd[4], sq[4], sk[4];
    int w = threadIdx.x >> 5;
    if ((threadIdx.x & 31) == 0) { sd[w] = dot; sq[w] = qq; sk[w] = kk; }
    __syncthreads();
    if (threadIdx.x == 0) {
        dot = sd[0] + sd[1] + sd[2] + sd[3];
        qq  = sq[0] + sq[1] + sq[2] + sq[3];
        kk  = sk[0] + sk[1] + sk[2] + sk[3];
        float denom = fmaxf(sqrtf(qq) * sqrtf(kk), 1e-8f);
        g_probs[token] = (1.0f - dot / denom) * 0.5f;
    }
}

// ---------------- Kernel 3: per-batch boundary scan + aux -------------------
__global__ __launch_bounds__(1024) void boundary_kernel()
{
    int b = blockIdx.x;
    int tid = threadIdx.x;
    __shared__ int   s[1024];
    __shared__ float sf[1024];

    int l0 = tid * 4;
    float p[4]; int bd[4]; int cnt = 0; float psum = 0.f;
#pragma unroll
    for (int i = 0; i < 4; i++) {
        int l = l0 + i;
        p[i] = g_probs[b * L + l];
        bd[i] = (l == 0) || (p[i] > 0.5f);
        cnt += bd[i];
        psum += p[i];
    }
    s[tid] = cnt;
    sf[tid] = psum;
    __syncthreads();
    for (int off = 1; off < 1024; off <<= 1) {
        int v = (tid >= off) ? s[tid - off] : 0;
        __syncthreads();
        if (tid >= off) s[tid] += v;
        __syncthreads();
    }
    int incl = s[tid];
    int base = incl - cnt;
    int total = s[1023];
    int run = base;
#pragma unroll
    for (int i = 0; i < 4; i++) {
        int l = l0 + i;
        if (bd[i]) { g_blidx[b * L + run] = l; run++; }
        g_chunkid[b * L + l] = run - 1;
    }
    __syncthreads();
    for (int off = 512; off > 0; off >>= 1) {
        if (tid < off) sf[tid] += sf[tid + off];
        __syncthreads();
    }
    if (tid == 0) {
        float F = (float)total / (float)L;
        float G = sf[0] / (float)L;
        g_auxb[b] = 1.2f * (5.0f * F * G + (1.0f - F) * (1.0f - G));
        g_nch[b] = total;
    }
}

// ---------------- Kernel 4a: zero padded chunk slots of downsampled ---------
__global__ __launch_bounds__(256) void zero_down_kernel(float* __restrict__ out)
{
    int row = blockIdx.x;          // b*L + j
    int b = row >> 12;
    int j = row & (L - 1);
    if (j < g_nch[b]) return;
    float4* o = (float4*)(out + (size_t)row * D);
    o[threadIdx.x] = make_float4(0.f, 0.f, 0.f, 0.f);
}

// ---------------- Kernel 4b: windowed-parallel chunk EMA scan ---------------
// Boundary chunks j>=1 have gate (1-p) < 0.5, so a 64-chunk warm-up gives
// error < 2^-64; slot 0's (possibly large) gate only affects the exact j0=0
// block, which starts from the true initial state.
__global__ __launch_bounds__(128) void chunk_scan_kernel(
    const float* __restrict__ tokens, float* __restrict__ out)
{
    int b = blockIdx.z;
    int nch = g_nch[b];
    int j0 = blockIdx.y * 128;
    if (j0 >= nch) return;
    int d = blockIdx.x * 128 + threadIdx.x;
    int jstart = (j0 >= 64) ? (j0 - 64) : 0;
    int jend = min(j0 + 128, nch);
    int cnt = jend - jstart;

    __shared__ int   sl[192];
    __shared__ float sp[192];
    for (int i = threadIdx.x; i < cnt; i += 128) {
        int l = g_blidx[b * L + jstart + i];
        sl[i] = l;
        sp[i] = g_probs[b * L + l];
    }
    __syncthreads();

    float h = 0.f;
    int i = 0;
    int warm = j0 - jstart;
    for (; i < warm; i++) {
        float p = sp[i];
        float t = tokens[((size_t)b * L + sl[i]) * D + d];
        h = fmaf(1.f - p, h, p * t);
    }
    for (; i < cnt; i++) {
        int j = jstart + i;
        float p = sp[i];
        float t = tokens[((size_t)b * L + sl[i]) * D + d];
        float x = p * t;
        out[((size_t)b * L + j) * D + d] = x;          // downsampled
        h = fmaf(1.f - p, h, x);
        g_scan[((size_t)b * L + j) * D + d] = h;
    }
}

// ---------------- Kernel 5: ups = gather(scan) + res + b_res ----------------
__global__ __launch_bounds__(256) void ups_kernel(
    float* __restrict__ out, const float* __restrict__ b_res)
{
    int row = blockIdx.x;          // b*L + l
    int b = row >> 12;
    int cid = g_chunkid[row];
    const float4* sc = (const float4*)(g_scan + (size_t)(b * L + cid) * D);
    const float4* rs = (const float4*)(g_res + (size_t)row * D);
    const float4* br = (const float4*)b_res;
    float4* o = (float4*)(out + BLD + (size_t)row * D);
    int t = threadIdx.x;
    float4 a = sc[t], c = rs[t], e = br[t];
    o[t] = make_float4(a.x + c.x + e.x, a.y + c.y + e.y,
                       a.z + c.z + e.z, a.w + c.w + e.w);
}

// ---------------- Kernel 6: finalize aux scalar -----------------------------
__global__ void aux_final_kernel(float* __restrict__ out)
{
    float s = 0.f;
    for (int i = 0; i < B; i++) s += g_auxb[i];
    out[2 * BLD] = (s / (float)B) * 0.03f;
}

// ---------------- launch ----------------------------------------------------
extern "C" void kernel_launch(void* const* d_in, const int* in_sizes, int n_in,
                              void* d_out, int out_size)
{
    const float* tokens = (const float*)d_in[0];
    const float* Wqk    = (const float*)d_in[1];
    const float* skey   = (const float*)d_in[2];
    const float* Wres   = (const float*)d_in[3];
    const float* bres   = (const float*)d_in[4];
    float* out = (float*)d_out;

    cudaFuncSetAttribute(gemm_kernel,
                         cudaFuncAttributeMaxDynamicSharedMemorySize, GEMM_SMEM);

    split_a_kernel<<<32768, 256>>>(tokens);                  // 33.5M/4/256
    split_b_kernel<<<1536, 256>>>(Wqk, Wres);                // 3072*128/256
    gemm_kernel<<<dim3(24, 256), 256, GEMM_SMEM>>>();
    probs_kernel<<<M, 128>>>(skey);
    boundary_kernel<<<B, 1024>>>();
    zero_down_kernel<<<M, 256>>>(out);
    chunk_scan_kernel<<<dim3(D / 128, L / 128, B), 128>>>(tokens, out);
    ups_kernel<<<M, 256>>>(out, bres);
    aux_final_kernel<<<1, 1>>>(out);
}

// round 6
// speedup vs baseline: 2.7498x; 1.1661x over previous
#include <cuda_runtime.h>
#include <cuda_bf16.h>
#include <cstdint>

#define B   8
#define L   4096
#define D   1024
#define DQK 1024
#define M   (B * L)           // 32768 tokens
#define BLD ((size_t)M * D)   // 33554432
#define NTOT 3072

// ---------------- scratch (device globals; no allocation allowed) ----------
__device__ float g_q[(size_t)M * DQK];     // 128 MiB
__device__ float g_k[(size_t)M * DQK];     // 128 MiB
__device__ float g_res[(size_t)M * D];     // 128 MiB
__device__ float g_scan[(size_t)M * D];    // 128 MiB
__device__ float g_probs[M];
__device__ int   g_flag[M];
__device__ int   g_chunkid[M];
__device__ int   g_blidx[M];
__device__ int   g_nch[B];
__device__ float g_auxb[B];

// bf16 2-way splits of A (tokens) and B (combined weights, TRANSPOSED: [n][k])
__device__ __nv_bfloat16 g_Ahi [(size_t)M * 1024];
__device__ __nv_bfloat16 g_Amid[(size_t)M * 1024];
__device__ __nv_bfloat16 g_Bhi [(size_t)NTOT * 1024];
__device__ __nv_bfloat16 g_Bmid[(size_t)NTOT * 1024];

// ======================= helpers ===========================================
__device__ __forceinline__ uint32_t smem_u32(const void* p) {
    uint32_t a;
    asm("{ .reg .u64 t; cvta.to.shared.u64 t, %1; cvt.u32.u64 %0, t; }"
        : "=r"(a) : "l"(p));
    return a;
}
__device__ __forceinline__ void cp_async16(uint32_t saddr, const void* gaddr) {
    asm volatile("cp.async.cg.shared.global [%0], [%1], 16;"
                 :: "r"(saddr), "l"(gaddr));
}
__device__ __forceinline__ void cp_commit() {
    asm volatile("cp.async.commit_group;");
}
template<int N> __device__ __forceinline__ void cp_waitg() {
    asm volatile("cp.async.wait_group %0;" :: "n"(N));
}
__device__ __forceinline__ void ldsm_x4(uint32_t addr, uint32_t& r0, uint32_t& r1,
                                        uint32_t& r2, uint32_t& r3) {
    asm volatile("ldmatrix.sync.aligned.m8n8.x4.shared.b16 {%0,%1,%2,%3}, [%4];"
                 : "=r"(r0), "=r"(r1), "=r"(r2), "=r"(r3) : "r"(addr));
}
__device__ __forceinline__ void mma_bf16(float* c,
                                         const uint32_t* a,
                                         uint32_t b0, uint32_t b1) {
    asm volatile(
        "mma.sync.aligned.m16n8k16.row.col.f32.bf16.bf16.f32 "
        "{%0,%1,%2,%3}, {%4,%5,%6,%7}, {%8,%9}, {%0,%1,%2,%3};"
        : "+f"(c[0]), "+f"(c[1]), "+f"(c[2]), "+f"(c[3])
        : "r"(a[0]), "r"(a[1]), "r"(a[2]), "r"(a[3]), "r"(b0), "r"(b1));
}

// ---------------- Prep 1: split tokens -> bf16 hi/mid -----------------------
__global__ __launch_bounds__(256) void split_a_kernel(const float* __restrict__ A)
{
    size_t i4 = (size_t)blockIdx.x * 256 + threadIdx.x;   // float4 index
    float4 v = ((const float4*)A)[i4];
    float x[4] = {v.x, v.y, v.z, v.w};
    unsigned short h[4], mm[4];
#pragma unroll
    for (int j = 0; j < 4; j++) {
        __nv_bfloat16 bh = __float2bfloat16_rn(x[j]);
        float r1 = x[j] - __bfloat162float(bh);
        __nv_bfloat16 bm = __float2bfloat16_rn(r1);
        h[j]  = __bfloat16_as_ushort(bh);
        mm[j] = __bfloat16_as_ushort(bm);
    }
    ((uint2*)g_Ahi)[i4]  = make_uint2((unsigned)h[0]  | ((unsigned)h[1]  << 16),
                                      (unsigned)h[2]  | ((unsigned)h[3]  << 16));
    ((uint2*)g_Amid)[i4] = make_uint2((unsigned)mm[0] | ((unsigned)mm[1] << 16),
                                      (unsigned)mm[2] | ((unsigned)mm[3] << 16));
}

// ---------------- Prep 2: split + transpose weights -> [n][k] bf16 ----------
__global__ __launch_bounds__(256) void split_b_kernel(
    const float* __restrict__ Wqk, const float* __restrict__ Wres)
{
    int id = blockIdx.x * 256 + threadIdx.x;   // 0..393215
    int n  = id % NTOT;
    int kg = id / NTOT;                         // 0..127
    int k0 = kg * 8;
    unsigned short h[8], mm[8];
#pragma unroll
    for (int j = 0; j < 8; j++) {
        int k = k0 + j;
        float x = (n < 2048) ? Wqk[(size_t)k * 2048 + n]
                             : Wres[(size_t)k * 1024 + (n - 2048)];
        __nv_bfloat16 bh = __float2bfloat16_rn(x);
        float r1 = x - __bfloat162float(bh);
        __nv_bfloat16 bm = __float2bfloat16_rn(r1);
        h[j]  = __bfloat16_as_ushort(bh);
        mm[j] = __bfloat16_as_ushort(bm);
    }
    size_t off = (size_t)n * 1024 + k0;  // bf16 elements
#define PACK4(a) make_uint4((unsigned)a[0] | ((unsigned)a[1] << 16), \
                            (unsigned)a[2] | ((unsigned)a[3] << 16), \
                            (unsigned)a[4] | ((unsigned)a[5] << 16), \
                            (unsigned)a[6] | ((unsigned)a[7] << 16))
    *(uint4*)((char*)g_Bhi  + off * 2) = PACK4(h);
    *(uint4*)((char*)g_Bmid + off * 2) = PACK4(mm);
#undef PACK4
}

// ---------------- Kernel 1: mma.sync split-bf16 GEMM (3 products) -----------
// C[M, 3072] = tokens @ [W_qk | W_res], products hi*hi + hi*mid + mid*hi.
// Element rel error ~4e-6; QK cosine sign protected by fixup_kernel.
// CTA tile 128x128, warps 4(m) x 2(n), warp tile 32x64, K-chunks of 64.
// 3-stage cp.async pipeline, 4 tiles (Ahi, Amid, Bhi, Bmid) per stage.
#define TILE_B      16384           // one 128x64 bf16 tile (128B rows)
#define STAGE_BYTES (4 * TILE_B)    // 64 KB
#define GEMM_SMEM   (3 * STAGE_BYTES)

__device__ __forceinline__ void fill_stage4(
    uint32_t st32, const char* const* gsrc, int chunk, int tid)
{
#pragma unroll
    for (int t = 0; t < 4; t++) {
#pragma unroll
        for (int it = 0; it < 4; it++) {
            int w = tid + it * 256;                    // 0..1023
            int row = w >> 3;
            int colB = (w & 7) * 16;
            const char* g = gsrc[t] + (size_t)row * 2048 + chunk * 128 + colB;
            uint32_t dst = st32 + t * TILE_B + row * 128
                         + (colB ^ ((row & 7) << 4));
            cp_async16(dst, g);
        }
    }
}

__global__ void __launch_bounds__(256, 1) gemm_kernel()
{
    extern __shared__ char smem[];
    uint32_t sb = smem_u32(smem);
    const int tid = threadIdx.x;
    const int lane = tid & 31;
    const int wid = tid >> 5;
    const int warp_m = wid & 3;          // m offset 32*warp_m
    const int warp_n = wid >> 2;         // n offset 64*warp_n
    const int m0 = blockIdx.y * 128;
    const int n0 = blockIdx.x * 128;

    const char* gsrc[4];
    gsrc[0] = (const char*)g_Ahi  + (size_t)m0 * 2048;
    gsrc[1] = (const char*)g_Amid + (size_t)m0 * 2048;
    gsrc[2] = (const char*)g_Bhi  + (size_t)n0 * 2048;
    gsrc[3] = (const char*)g_Bmid + (size_t)n0 * 2048;

    float acc[2][8][4];
#pragma unroll
    for (int i = 0; i < 2; i++)
#pragma unroll
        for (int j = 0; j < 8; j++)
#pragma unroll
            for (int q = 0; q < 4; q++) acc[i][j][q] = 0.f;

    // per-thread ldmatrix address invariants
    const int aRow  = warp_m * 32 + (lane & 15);       // +16*mi later
    const int aXor  = (aRow & 7) << 4;
    const int aColB = (lane >> 4) * 16;                // 0/16
    const int bRow  = warp_n * 64 + (lane & 7) + ((lane >> 4) & 1) * 8; // +16*ng
    const int bXor  = (bRow & 7) << 4;
    const int bColB = ((lane >> 3) & 1) * 16;          // 0/16

    fill_stage4(sb, gsrc, 0, tid);
    cp_commit();
    fill_stage4(sb + STAGE_BYTES, gsrc, 1, tid);
    cp_commit();

    for (int c = 0; c < 16; c++) {
        uint32_t stage = sb + (c % 3) * STAGE_BYTES;
        if (c < 14) {
            fill_stage4(sb + ((c + 2) % 3) * STAGE_BYTES, gsrc, c + 2, tid);
            cp_commit();
            cp_waitg<2>();
        } else if (c == 14) {
            cp_waitg<1>();
        } else {
            cp_waitg<0>();
        }
        __syncthreads();

        uint32_t aHi = stage, aMid = stage + TILE_B;
        uint32_t bHi = stage + 2 * TILE_B, bMid = stage + 3 * TILE_B;
#pragma unroll
        for (int ks = 0; ks < 4; ks++) {
            uint32_t ah[2][4], am[2][4];
#pragma unroll
            for (int mi = 0; mi < 2; mi++) {
                uint32_t roff = (aRow + mi * 16) * 128 + ((ks * 32 + aColB) ^ aXor);
                ldsm_x4(aHi  + roff, ah[mi][0], ah[mi][1], ah[mi][2], ah[mi][3]);
                ldsm_x4(aMid + roff, am[mi][0], am[mi][1], am[mi][2], am[mi][3]);
            }
            uint32_t bh[4][4], bm[4][4];
#pragma unroll
            for (int ng = 0; ng < 4; ng++) {
                uint32_t roff = (bRow + ng * 16) * 128 + ((ks * 32 + bColB) ^ bXor);
                ldsm_x4(bHi  + roff, bh[ng][0], bh[ng][1], bh[ng][2], bh[ng][3]);
                ldsm_x4(bMid + roff, bm[ng][0], bm[ng][1], bm[ng][2], bm[ng][3]);
            }
#pragma unroll
            for (int mi = 0; mi < 2; mi++)
#pragma unroll
                for (int ng = 0; ng < 4; ng++) {
                    // hi*hi
                    mma_bf16(acc[mi][ng*2],   ah[mi], bh[ng][0], bh[ng][1]);
                    mma_bf16(acc[mi][ng*2+1], ah[mi], bh[ng][2], bh[ng][3]);
                    // hi*mid
                    mma_bf16(acc[mi][ng*2],   ah[mi], bm[ng][0], bm[ng][1]);
                    mma_bf16(acc[mi][ng*2+1], ah[mi], bm[ng][2], bm[ng][3]);
                    // mid*hi
                    mma_bf16(acc[mi][ng*2],   am[mi], bh[ng][0], bh[ng][1]);
                    mma_bf16(acc[mi][ng*2+1], am[mi], bh[ng][2], bh[ng][3]);
                }
        }
        __syncthreads();
    }

    float* cbase; int coloff;
    if (n0 < 1024)      { cbase = g_q;   coloff = n0; }
    else if (n0 < 2048) { cbase = g_k;   coloff = n0 - 1024; }
    else                { cbase = g_res; coloff = n0 - 2048; }

#pragma unroll
    for (int mi = 0; mi < 2; mi++) {
        int r0 = m0 + warp_m * 32 + mi * 16 + (lane >> 2);
#pragma unroll
        for (int ni = 0; ni < 8; ni++) {
            int col = coloff + warp_n * 64 + ni * 8 + (lane & 3) * 2;
            *(float2*)&cbase[(size_t)r0 * 1024 + col] =
                make_float2(acc[mi][ni][0], acc[mi][ni][1]);
            *(float2*)&cbase[(size_t)(r0 + 8) * 1024 + col] =
                make_float2(acc[mi][ni][2], acc[mi][ni][3]);
        }
    }
}

// ---------------- Kernel 2: per-token cosine -> probs + near-zero flag ------
__global__ __launch_bounds__(128) void probs_kernel(const float* __restrict__ start_key)
{
    int token = blockIdx.x;
    int l = token & (L - 1);
    const float4* qv = (const float4*)(g_q + (size_t)token * DQK);
    const float4* kv = (l == 0) ? (const float4*)start_key
                                : (const float4*)(g_k + (size_t)(token - 1) * DQK);
    float dot = 0.f, qq = 0.f, kk = 0.f;
    for (int i = threadIdx.x; i < DQK / 4; i += 128) {
        float4 a = qv[i], c = kv[i];
        dot += a.x * c.x + a.y * c.y + a.z * c.z + a.w * c.w;
        qq  += a.x * a.x + a.y * a.y + a.z * a.z + a.w * a.w;
        kk  += c.x * c.x + c.y * c.y + c.z * c.z + c.w * c.w;
    }
#pragma unroll
    for (int o = 16; o; o >>= 1) {
        dot += __shfl_down_sync(0xffffffffu, dot, o);
        qq  += __shfl_down_sync(0xffffffffu, qq,  o);
        kk  += __shfl_down_sync(0xffffffffu, kk,  o);
    }
    __shared__ float sd[4], sq[4], sk[4];
    int w = threadIdx.x >> 5;
    if ((threadIdx.x & 31) == 0) { sd[w] = dot; sq[w] = qq; sk[w] = kk; }
    __syncthreads();
    if (threadIdx.x == 0) {
        dot = sd[0] + sd[1] + sd[2] + sd[3];
        qq  = sq[0] + sq[1] + sq[2] + sq[3];
        kk  = sk[0] + sk[1] + sk[2] + sk[3];
        float denom = fmaxf(sqrtf(qq) * sqrtf(kk), 1e-8f);
        float cosv = dot / denom;
        g_probs[token] = (1.0f - cosv) * 0.5f;
        g_flag[token] = (fabsf(cosv) < 2.5e-4f) ? 1 : 0;
    }
}

// ---------------- Kernel 2b: exact fp32 fixup for near-threshold tokens -----
// Recomputes q = Wq^T t, k = Wk^T t_prev and the cosine in full fp32 for the
// ~0.3% of tokens whose 3-product cosine is within 2.5e-4 of zero (the
// boundary decision margin). Everything else keeps the cheap value.
__global__ __launch_bounds__(256) void fixup_kernel(
    const float* __restrict__ tokens, const float* __restrict__ Wqk,
    const float* __restrict__ start_key)
{
    int token = blockIdx.x;
    if (!g_flag[token]) return;
    int l = token & (L - 1);
    int tid = threadIdx.x;

    __shared__ float cur[1024], prev[1024];
    __shared__ float qv[1024], kv[1024];
    __shared__ float red[3][8];

    for (int i = tid; i < 1024; i += 256) {
        cur[i]  = tokens[(size_t)token * D + i];
        prev[i] = (l > 0) ? tokens[(size_t)(token - 1) * D + i] : 0.f;
    }
    __syncthreads();

#pragma unroll
    for (int j = 0; j < 4; j++) {
        int e = tid + j * 256;                 // q column
        float accq = 0.f;
        for (int d = 0; d < 1024; d++)
            accq = fmaf(cur[d], Wqk[(size_t)d * 2048 + e], accq);
        qv[e] = accq;
        if (l > 0) {
            float acck = 0.f;
            for (int d = 0; d < 1024; d++)
                acck = fmaf(prev[d], Wqk[(size_t)d * 2048 + 1024 + e], acck);
            kv[e] = acck;
        } else {
            kv[e] = start_key[e];
        }
    }
    __syncthreads();

    float dot = 0.f, qq = 0.f, kk = 0.f;
    for (int i = tid; i < 1024; i += 256) {
        float a = qv[i], c = kv[i];
        dot = fmaf(a, c, dot); qq = fmaf(a, a, qq); kk = fmaf(c, c, kk);
    }
#pragma unroll
    for (int o = 16; o; o >>= 1) {
        dot += __shfl_down_sync(0xffffffffu, dot, o);
        qq  += __shfl_down_sync(0xffffffffu, qq,  o);
        kk  += __shfl_down_sync(0xffffffffu, kk,  o);
    }
    int w = tid >> 5;
    if ((tid & 31) == 0) { red[0][w] = dot; red[1][w] = qq; red[2][w] = kk; }
    __syncthreads();
    if (tid == 0) {
        dot = 0.f; qq = 0.f; kk = 0.f;
#pragma unroll
        for (int i = 0; i < 8; i++) { dot += red[0][i]; qq += red[1][i]; kk += red[2][i]; }
        float denom = fmaxf(sqrtf(qq) * sqrtf(kk), 1e-8f);
        g_probs[token] = (1.0f - dot / denom) * 0.5f;
    }
}

// ---------------- Kernel 3: per-batch boundary scan + aux -------------------
__global__ __launch_bounds__(1024) void boundary_kernel()
{
    int b = blockIdx.x;
    int tid = threadIdx.x;
    __shared__ int   s[1024];
    __shared__ float sf[1024];

    int l0 = tid * 4;
    float p[4]; int bd[4]; int cnt = 0; float psum = 0.f;
#pragma unroll
    for (int i = 0; i < 4; i++) {
        int l = l0 + i;
        p[i] = g_probs[b * L + l];
        bd[i] = (l == 0) || (p[i] > 0.5f);
        cnt += bd[i];
        psum += p[i];
    }
    s[tid] = cnt;
    sf[tid] = psum;
    __syncthreads();
    for (int off = 1; off < 1024; off <<= 1) {
        int v = (tid >= off) ? s[tid - off] : 0;
        __syncthreads();
        if (tid >= off) s[tid] += v;
        __syncthreads();
    }
    int incl = s[tid];
    int base = incl - cnt;
    int total = s[1023];
    int run = base;
#pragma unroll
    for (int i = 0; i < 4; i++) {
        int l = l0 + i;
        if (bd[i]) { g_blidx[b * L + run] = l; run++; }
        g_chunkid[b * L + l] = run - 1;
    }
    __syncthreads();
    for (int off = 512; off > 0; off >>= 1) {
        if (tid < off) sf[tid] += sf[tid + off];
        __syncthreads();
    }
    if (tid == 0) {
        float F = (float)total / (float)L;
        float G = sf[0] / (float)L;
        g_auxb[b] = 1.2f * (5.0f * F * G + (1.0f - F) * (1.0f - G));
        g_nch[b] = total;
    }
}

// ---------------- Kernel 4a: zero padded chunk slots of downsampled ---------
__global__ __launch_bounds__(256) void zero_down_kernel(float* __restrict__ out)
{
    int row = blockIdx.x;          // b*L + j
    int b = row >> 12;
    int j = row & (L - 1);
    if (j < g_nch[b]) return;
    float4* o = (float4*)(out + (size_t)row * D);
    o[threadIdx.x] = make_float4(0.f, 0.f, 0.f, 0.f);
}

// ---------------- Kernel 4b: windowed-parallel chunk EMA scan ---------------
// Boundary chunks j>=1 have gate (1-p) < 0.5, so a 64-chunk warm-up gives
// error < 2^-64; the j0=0 block starts from the true initial state.
__global__ __launch_bounds__(128) void chunk_scan_kernel(
    const float* __restrict__ tokens, float* __restrict__ out)
{
    int b = blockIdx.z;
    int nch = g_nch[b];
    int j0 = blockIdx.y * 128;
    if (j0 >= nch) return;
    int d = blockIdx.x * 128 + threadIdx.x;
    int jstart = (j0 >= 64) ? (j0 - 64) : 0;
    int jend = min(j0 + 128, nch);
    int cnt = jend - jstart;

    __shared__ int   sl[192];
    __shared__ float sp[192];
    for (int i = threadIdx.x; i < cnt; i += 128) {
        int l = g_blidx[b * L + jstart + i];
        sl[i] = l;
        sp[i] = g_probs[b * L + l];
    }
    __syncthreads();

    float h = 0.f;
    int i = 0;
    int warm = j0 - jstart;
    for (; i < warm; i++) {
        float p = sp[i];
        float t = tokens[((size_t)b * L + sl[i]) * D + d];
        h = fmaf(1.f - p, h, p * t);
    }
    for (; i < cnt; i++) {
        int j = jstart + i;
        float p = sp[i];
        float t = tokens[((size_t)b * L + sl[i]) * D + d];
        float x = p * t;
        out[((size_t)b * L + j) * D + d] = x;          // downsampled
        h = fmaf(1.f - p, h, x);
        g_scan[((size_t)b * L + j) * D + d] = h;
    }
}

// ---------------- Kernel 5: ups = gather(scan) + res + b_res ----------------
__global__ __launch_bounds__(256) void ups_kernel(
    float* __restrict__ out, const float* __restrict__ b_res)
{
    int row = blockIdx.x;          // b*L + l
    int b = row >> 12;
    int cid = g_chunkid[row];
    const float4* sc = (const float4*)(g_scan + (size_t)(b * L + cid) * D);
    const float4* rs = (const float4*)(g_res + (size_t)row * D);
    const float4* br = (const float4*)b_res;
    float4* o = (float4*)(out + BLD + (size_t)row * D);
    int t = threadIdx.x;
    float4 a = sc[t], c = rs[t], e = br[t];
    o[t] = make_float4(a.x + c.x + e.x, a.y + c.y + e.y,
                       a.z + c.z + e.z, a.w + c.w + e.w);
}

// ---------------- Kernel 6: finalize aux scalar -----------------------------
__global__ void aux_final_kernel(float* __restrict__ out)
{
    float s = 0.f;
    for (int i = 0; i < B; i++) s += g_auxb[i];
    out[2 * BLD] = (s / (float)B) * 0.03f;
}

// ---------------- launch ----------------------------------------------------
extern "C" void kernel_launch(void* const* d_in, const int* in_sizes, int n_in,
                              void* d_out, int out_size)
{
    const float* tokens = (const float*)d_in[0];
    const float* Wqk    = (const float*)d_in[1];
    const float* skey   = (const float*)d_in[2];
    const float* Wres   = (const float*)d_in[3];
    const float* bres   = (const float*)d_in[4];
    float* out = (float*)d_out;

    cudaFuncSetAttribute(gemm_kernel,
                         cudaFuncAttributeMaxDynamicSharedMemorySize, GEMM_SMEM);

    split_a_kernel<<<32768, 256>>>(tokens);                  // 33.5M/4/256
    split_b_kernel<<<1536, 256>>>(Wqk, Wres);                // 3072*128/256
    gemm_kernel<<<dim3(24, 256), 256, GEMM_SMEM>>>();
    probs_kernel<<<M, 128>>>(skey);
    fixup_kernel<<<M, 256>>>(tokens, Wqk, skey);
    boundary_kernel<<<B, 1024>>>();
    zero_down_kernel<<<M, 256>>>(out);
    chunk_scan_kernel<<<dim3(D / 128, L / 128, B), 128>>>(tokens, out);
    ups_kernel<<<M, 256>>>(out, bres);
    aux_final_kernel<<<1, 1>>>(out);
}